// round 16
// baseline (speedup 1.0000x reference)
#include <cuda_runtime.h>
#include <cuda_bf16.h>
#include <cstdint>
#include <cstddef>

#define Nn   100000
#define Ee   256000
#define EMB  300
#define EMB2 600
#define LAYERS 5

#define KP1 320
#define KP2 640
#define NCHA 10     // KP1/32
#define NCHB 20     // KP2/32 (chunks of 32 K-cols)
#define NPAD1 640   // 10 n-tiles of 64
#define NPAD2 320   // 5 n-tiles of 64

// ---------------- device scratch ----------------
__device__ __align__(128) float  g_z1   [(size_t)Nn * EMB2];
__device__ __align__(128) float  g_z2   [(size_t)Nn * EMB];
__device__ __align__(128) __nv_bfloat16 g_Ahi[(size_t)Nn * KP1];
__device__ __align__(128) __nv_bfloat16 g_Alo[(size_t)Nn * KP1];
__device__ __align__(128) __nv_bfloat16 g_Bhi[262144];
__device__ __align__(128) __nv_bfloat16 g_Blo[262144];
__device__ __align__(16) float g_etab [9 * EMB];
__device__ double g_sum  [EMB2];
__device__ double g_sq   [EMB2];
__device__ __align__(16) float  g_sc1  [EMB2];
__device__ __align__(16) float  g_sh1  [EMB2];
__device__ __align__(16) float  g_sc2  [EMB];
__device__ __align__(16) float  g_sh2  [EMB];
// CSR (built once per launch)
__device__ int g_rowptr[Nn + 1];
__device__ int g_cnt   [Nn];
__device__ int g_elist [Ee];

// ---------------- PTX helpers ----------------
__device__ __forceinline__ uint32_t smem_u32(const void* p) {
    uint32_t a;
    asm("{ .reg .u64 t; cvta.to.shared.u64 t, %1; cvt.u32.u64 %0, t; }" : "=r"(a) : "l"(p));
    return a;
}
__device__ __forceinline__ void cp_async16(uint32_t dst, const void* src) {
    asm volatile("cp.async.cg.shared.global [%0], [%1], 16;" :: "r"(dst), "l"(src));
}
__device__ __forceinline__ void cp_async16p(uint32_t dst, const void* src, bool valid) {
    int sz = valid ? 16 : 0;
    asm volatile("cp.async.cg.shared.global [%0], [%1], 16, %2;" :: "r"(dst), "l"(src), "r"(sz));
}
__device__ __forceinline__ void cp_commit() { asm volatile("cp.async.commit_group;"); }
__device__ __forceinline__ uint32_t swz64(uint32_t b) { return b ^ ((b >> 3) & 0x30); }

__device__ __forceinline__ void ldsm_x4(uint32_t (&r)[4], uint32_t addr) {
    asm volatile("ldmatrix.sync.aligned.m8n8.x4.shared.b16 {%0,%1,%2,%3}, [%4];"
        : "=r"(r[0]), "=r"(r[1]), "=r"(r[2]), "=r"(r[3]) : "r"(addr));
}
__device__ __forceinline__ void mma16816(float (&d)[4], const uint32_t (&a)[4],
                                         uint32_t b0, uint32_t b1) {
    asm volatile("mma.sync.aligned.m16n8k16.row.col.f32.bf16.bf16.f32 "
        "{%0,%1,%2,%3}, {%4,%5,%6,%7}, {%8,%9}, {%0,%1,%2,%3};"
        : "+f"(d[0]), "+f"(d[1]), "+f"(d[2]), "+f"(d[3])
        : "r"(a[0]), "r"(a[1]), "r"(a[2]), "r"(a[3]), "r"(b0), "r"(b1));
}
__device__ __forceinline__ void sts64(uint32_t addr, uint32_t a, uint32_t b) {
    asm volatile("st.shared.v2.b32 [%0], {%1,%2};" :: "r"(addr), "r"(a), "r"(b));
}

// ---------------- CSR build (once per launch) ----------------
__global__ void csr_zero() {
    int i = blockIdx.x * blockDim.x + threadIdx.x;
    if (i < Nn) g_cnt[i] = 0;
}
__global__ void csr_count(const int* __restrict__ ei) {
    int e = blockIdx.x * blockDim.x + threadIdx.x;
    if (e < Ee) atomicAdd(&g_cnt[ei[Ee + e]], 1);
}
__global__ void __launch_bounds__(1024) csr_scan() {
    __shared__ int sums[1024];
    int t = threadIdx.x;
    const int CH = (Nn + 1023) / 1024;
    int start = t * CH;
    int end = min(start + CH, Nn);
    int s = 0;
    for (int i = start; i < end; i++) s += g_cnt[i];
    sums[t] = s;
    __syncthreads();
    for (int off = 1; off < 1024; off <<= 1) {
        int v = (t >= off) ? sums[t - off] : 0;
        __syncthreads();
        sums[t] += v;
        __syncthreads();
    }
    int run = (t == 0) ? 0 : sums[t - 1];
    for (int i = start; i < end; i++) { g_rowptr[i] = run; run += g_cnt[i]; }
    if (t == 1023) g_rowptr[Nn] = sums[1023];
    __syncthreads();
    for (int i = start; i < end; i++) g_cnt[i] = 0;
}
__global__ void csr_fill(const int* __restrict__ ei) {
    int e = blockIdx.x * blockDim.x + threadIdx.x;
    if (e < Ee) {
        int dst = ei[Ee + e];
        int pos = atomicAdd(&g_cnt[dst], 1);
        g_elist[g_rowptr[dst] + pos] = e;
    }
}

// ---------------- fused gather + BN-inline + bf16 split (feeds GEMM1) ----------------
template <int FIRST>
__global__ void __launch_bounds__(512)
gather_split(const float* __restrict__ Z, const int* __restrict__ ei,
             const int* __restrict__ ea, const float* __restrict__ eps, int l) {
    __shared__ __align__(16) float s_et[9 * EMB];
    for (int i = threadIdx.x; i < 9 * EMB; i += 512) s_et[i] = g_etab[i];
    __syncthreads();

    int warp = threadIdx.x >> 5, lane = threadIdx.x & 31;
    int n = blockIdx.x * 16 + warp;
    if (n >= Nn) return;

    float4 cs[3], ds[3];
    if (!FIRST) {
#pragma unroll
        for (int t = 0; t < 3; t++) {
            int k = lane + t * 32;
            if (k < 75) {
                cs[t] = *reinterpret_cast<const float4*>(g_sc2 + k * 4);
                ds[t] = *reinterpret_cast<const float4*>(g_sh2 + k * 4);
            }
        }
    }

    auto bn = [&](float4 z, int t) -> float4 {
        if (FIRST) return z;
        float4 o;
        o.x = fmaxf(fmaf(cs[t].x, z.x, ds[t].x), 0.f);
        o.y = fmaxf(fmaf(cs[t].y, z.y, ds[t].y), 0.f);
        o.z = fmaxf(fmaf(cs[t].z, z.z, ds[t].z), 0.f);
        o.w = fmaxf(fmaf(cs[t].w, z.w, ds[t].w), 0.f);
        return o;
    };

    float4 acc[3];
#pragma unroll
    for (int t = 0; t < 3; t++) acc[t] = make_float4(0.f, 0.f, 0.f, 0.f);

    int beg = __ldg(g_rowptr + n), stop = __ldg(g_rowptr + n + 1);
    for (int idx = beg; idx < stop; idx++) {
        int e   = __ldg(g_elist + idx);
        int src = __ldg(ei + e);
        int c   = __ldg(ea + 2 * e) * 3 + __ldg(ea + 2 * e + 1);
        const float4* zr = reinterpret_cast<const float4*>(Z + (size_t)src * EMB);
        const float4* er = reinterpret_cast<const float4*>(s_et + c * EMB);
#pragma unroll
        for (int t = 0; t < 3; t++) {
            int k = lane + t * 32;
            if (k < 75) {
                float4 hv = bn(__ldg(zr + k), t);
                float4 ev = er[k];
                acc[t].x += fmaxf(hv.x + ev.x, 0.f);
                acc[t].y += fmaxf(hv.y + ev.y, 0.f);
                acc[t].z += fmaxf(hv.z + ev.z, 0.f);
                acc[t].w += fmaxf(hv.w + ev.w, 0.f);
            }
        }
    }

    float f = 1.0f + __ldg(eps + l);
    const float4* zd = reinterpret_cast<const float4*>(Z + (size_t)n * EMB);
#pragma unroll
    for (int t = 0; t < 3; t++) {
        int k = lane + t * 32;
        if (k < 80) {
            float4 o = make_float4(0.f, 0.f, 0.f, 0.f);
            if (k < 75) {
                float4 hv = bn(__ldg(zd + k), t);
                o.x = fmaf(f, hv.x, acc[t].x);
                o.y = fmaf(f, hv.y, acc[t].y);
                o.z = fmaf(f, hv.z, acc[t].z);
                o.w = fmaf(f, hv.w, acc[t].w);
            }
            __nv_bfloat162 H0 = __floats2bfloat162_rn(o.x, o.y);
            __nv_bfloat162 H1 = __floats2bfloat162_rn(o.z, o.w);
            __nv_bfloat162 L0 = __floats2bfloat162_rn(o.x - __low2float(H0), o.y - __high2float(H0));
            __nv_bfloat162 L1 = __floats2bfloat162_rn(o.z - __low2float(H1), o.w - __high2float(H1));
            uint2 hv2 = make_uint2(*reinterpret_cast<uint32_t*>(&H0), *reinterpret_cast<uint32_t*>(&H1));
            uint2 lv2 = make_uint2(*reinterpret_cast<uint32_t*>(&L0), *reinterpret_cast<uint32_t*>(&L1));
            *reinterpret_cast<uint2*>(g_Ahi + (size_t)n * KP1 + k * 4) = hv2;
            *reinterpret_cast<uint2*>(g_Alo + (size_t)n * KP1 + k * 4) = lv2;
        }
    }
}

// ---------------- prep kernels ----------------
__global__ void prep1(const float* __restrict__ W1, const float* __restrict__ Wb) {
    int b = blockIdx.x, t = threadIdx.x;
    if (b < NPAD1) {
        float v = (b < EMB2 && t < EMB) ? W1[(size_t)b * EMB + t] : 0.0f;
        __nv_bfloat16 h = __float2bfloat16_rn(v);
        g_Bhi[(size_t)b * KP1 + t] = h;
        g_Blo[(size_t)b * KP1 + t] = __float2bfloat16_rn(v - __bfloat162float(h));
    } else if (b < NPAD1 + 9) {
        int c = b - NPAD1;
        if (t < EMB) g_etab[c * EMB + t] = Wb[t * 9 + c / 3] + Wb[t * 9 + 6 + (c % 3)];
    } else {
        for (int i = t; i < EMB2; i += blockDim.x) { g_sum[i] = 0.0; g_sq[i] = 0.0; }
    }
}

__global__ void prep2(const float* __restrict__ W2,
                      const float* __restrict__ gamma, const float* __restrict__ beta) {
    int b = blockIdx.x, t = threadIdx.x;
    if (b < NPAD2) {
        for (int c = t; c < KP2; c += blockDim.x) {
            float v = (b < EMB && c < EMB2) ? W2[(size_t)b * EMB2 + c] : 0.0f;
            __nv_bfloat16 h = __float2bfloat16_rn(v);
            g_Bhi[(size_t)b * KP2 + c] = h;
            g_Blo[(size_t)b * KP2 + c] = __float2bfloat16_rn(v - __bfloat162float(h));
        }
    } else {
        for (int i = t; i < EMB2; i += blockDim.x) {
            double m = g_sum[i] / (double)Nn;
            double v = g_sq[i] / (double)Nn - m * m;
            float rs = rsqrtf((float)v + 1e-5f);
            float a = gamma[i] * rs;
            g_sc1[i] = a;
            g_sh1[i] = beta[i] - a * (float)m;
        }
        __syncthreads();
        for (int i = t; i < EMB; i += blockDim.x) { g_sum[i] = 0.0; g_sq[i] = 0.0; }
    }
}

__global__ void bn_finalize2(const float* __restrict__ gamma, const float* __restrict__ beta) {
    int i = blockIdx.x * blockDim.x + threadIdx.x;
    if (i >= EMB) return;
    double m = g_sum[i] / (double)Nn;
    double v = g_sq[i] / (double)Nn - m * m;
    float rs = rsqrtf((float)v + 1e-5f);
    float a = gamma[i] * rs;
    g_sc2[i] = a;
    g_sh2[i] = beta[i] - a * (float)m;
}

__global__ void bn_apply(const float* __restrict__ Z, float* __restrict__ outh) {
    int i = blockIdx.x * blockDim.x + threadIdx.x;
    if (i >= Nn * EMB) return;
    int col = i % EMB;
    outh[i] = fmaf(g_sc2[col], Z[i], g_sh2[col]);
}

// ---------------- GEMM1: lean split-bf16, pre-split A, 3 CTAs/SM (R15 proven) -------
__global__ void __launch_bounds__(256, 3)
gemm_s32(const __nv_bfloat16* __restrict__ Ahi, const __nv_bfloat16* __restrict__ Alo,
         const __nv_bfloat16* __restrict__ Bhi, const __nv_bfloat16* __restrict__ Blo,
         float* __restrict__ C, int M, int NC, int KP, int nch) {
    extern __shared__ __align__(1024) char smem[];
    uint32_t sb = smem_u32(smem);
    const int STAGE = 24576;

    int tid = threadIdx.x;
    int wid = tid >> 5, lane = tid & 31;
    int wm = wid >> 1, wn = wid & 1;
    int n0 = blockIdx.x * 64;
    int m0 = blockIdx.y * 128;

    int quad = lane >> 3, r = lane & 7;
    int arow_base = wm * 32 + (quad & 1) * 8 + r;
    int brow_base = wn * 32 + (quad & 1) * 8 + r;
    int khalf = quad >> 1;

    float acc[2][4][4];
#pragma unroll
    for (int mi = 0; mi < 2; mi++)
#pragma unroll
        for (int nt = 0; nt < 4; nt++)
#pragma unroll
            for (int q = 0; q < 4; q++) acc[mi][nt][q] = 0.0f;

    auto load_chunk = [&](int kc, int buf) {
        uint32_t s0 = sb + buf * STAGE;
        size_t aoff = (size_t)m0 * KP + (size_t)kc * 32;
        size_t boff = (size_t)n0 * KP + (size_t)kc * 32;
#pragma unroll
        for (int i = 0; i < 2; i++) {
            int seg = tid + i * 256;
            int row = seg >> 2, s = seg & 3;
            uint32_t so = swz64(row * 64 + s * 16);
            size_t ra = aoff + (size_t)row * KP + s * 8;
            bool va = (m0 + row) < M;
            cp_async16p(s0 + so,        Ahi + ra, va);
            cp_async16p(s0 + 8192 + so, Alo + ra, va);
        }
        {
            int row = tid >> 2, s = tid & 3;
            uint32_t so = swz64(row * 64 + s * 16);
            size_t rb = boff + (size_t)row * KP + s * 8;
            cp_async16(s0 + 16384 + so, Bhi + rb);
            cp_async16(s0 + 20480 + so, Blo + rb);
        }
        cp_commit();
    };

    load_chunk(0, 0);
    load_chunk(1, 1);

    for (int j = 0; j < nch; j++) {
        if (j + 2 < nch) asm volatile("cp.async.wait_group 1;" ::: "memory");
        else             asm volatile("cp.async.wait_group 0;" ::: "memory");
        __syncthreads();

        if (j + 2 < nch) load_chunk(j + 2, (j + 2) % 3);

        uint32_t s0 = sb + (j % 3) * STAGE;
#pragma unroll
        for (int ks = 0; ks < 2; ks++) {
            int seg = ks * 2 + khalf;
            uint32_t a[2][4], bh[2][4], bl[2][4];

#pragma unroll
            for (int mi = 0; mi < 2; mi++)
                ldsm_x4(a[mi], s0 + swz64((arow_base + mi * 16) * 64 + seg * 16));
#pragma unroll
            for (int nj = 0; nj < 2; nj++)
                ldsm_x4(bh[nj], s0 + 16384 + swz64((brow_base + nj * 16) * 64 + seg * 16));

#pragma unroll
            for (int mi = 0; mi < 2; mi++)
#pragma unroll
                for (int nt = 0; nt < 4; nt++)
                    mma16816(acc[mi][nt], a[mi], bh[nt >> 1][nt & 1], bh[nt >> 1][(nt & 1) + 2]);

#pragma unroll
            for (int nj = 0; nj < 2; nj++)
                ldsm_x4(bl[nj], s0 + 20480 + swz64((brow_base + nj * 16) * 64 + seg * 16));
#pragma unroll
            for (int mi = 0; mi < 2; mi++)
#pragma unroll
                for (int nt = 0; nt < 4; nt++)
                    mma16816(acc[mi][nt], a[mi], bl[nt >> 1][nt & 1], bl[nt >> 1][(nt & 1) + 2]);

#pragma unroll
            for (int mi = 0; mi < 2; mi++)
                ldsm_x4(a[mi], s0 + 8192 + swz64((arow_base + mi * 16) * 64 + seg * 16));
#pragma unroll
            for (int mi = 0; mi < 2; mi++)
#pragma unroll
                for (int nt = 0; nt < 4; nt++)
                    mma16816(acc[mi][nt], a[mi], bh[nt >> 1][nt & 1], bh[nt >> 1][(nt & 1) + 2]);
        }
    }

    int rg = lane >> 2, cg = (lane & 3) * 2;
#pragma unroll
    for (int mi = 0; mi < 2; mi++) {
        int r0 = m0 + wm * 32 + mi * 16 + rg;
#pragma unroll
        for (int nt = 0; nt < 4; nt++) {
            int c0 = n0 + wn * 32 + nt * 8 + cg;
            if (c0 < NC) {
                if (r0 < M)
                    *reinterpret_cast<float2*>(C + (size_t)r0 * NC + c0) =
                        make_float2(acc[mi][nt][0], acc[mi][nt][1]);
                if (r0 + 8 < M)
                    *reinterpret_cast<float2*>(C + (size_t)(r0 + 8) * NC + c0) =
                        make_float2(acc[mi][nt][2], acc[mi][nt][3]);
            }
        }
    }

#pragma unroll
    for (int nt = 0; nt < 4; nt++) {
#pragma unroll
        for (int cp = 0; cp < 2; cp++) {
            float s = 0.f, q = 0.f;
#pragma unroll
            for (int mi = 0; mi < 2; mi++) {
                float v0 = acc[mi][nt][cp];
                float v1 = acc[mi][nt][cp + 2];
                s += v0 + v1;
                q += v0 * v0 + v1 * v1;
            }
#pragma unroll
            for (int off = 4; off <= 16; off <<= 1) {
                s += __shfl_xor_sync(0xFFFFFFFF, s, off);
                q += __shfl_xor_sync(0xFFFFFFFF, q, off);
            }
            if ((lane >> 2) == 0) {
                int c0 = n0 + wn * 32 + nt * 8 + (lane & 3) * 2 + cp;
                if (c0 < NC) {
                    atomicAdd(&g_sum[c0], (double)s);
                    atomicAdd(&g_sq[c0], (double)q);
                }
            }
        }
    }
}

// ---------------- GEMM2: fused BN1+relu+split in A-load, z1 fp32 source -------------
// A chunk (128x32 fp32) loaded to regs, transformed, split to smem bf16 hi/lo.
// 3 A bufs (16KB) + 3 B bufs (8KB) = 72KB; 2 CTAs/SM. Frag-reuse phases hh->hl->lh.
__global__ void __launch_bounds__(256, 2)
gemm_fused2(const float* __restrict__ Z1,
            const __nv_bfloat16* __restrict__ Bhi, const __nv_bfloat16* __restrict__ Blo,
            float* __restrict__ C, int M) {
    extern __shared__ __align__(1024) char smem[];
    uint32_t sb = smem_u32(smem);
    const int ASTAGE = 16384;                 // hi 8K + lo 8K
    const uint32_t BB = 3 * ASTAGE;           // B region base (49152)
    const int BSTAGE = 8192;                  // hi 4K + lo 4K
    const int NC = EMB, nch = NCHB;

    int tid = threadIdx.x;
    int wid = tid >> 5, lane = tid & 31;
    int wm = wid >> 1, wn = wid & 1;
    int n0 = blockIdx.x * 64;
    int m0 = blockIdx.y * 128;

    int quad = lane >> 3, r = lane & 7;
    int arow_base = wm * 32 + (quad & 1) * 8 + r;
    int brow_base = wn * 32 + (quad & 1) * 8 + r;
    int khalf = quad >> 1;

    float acc[2][4][4];
#pragma unroll
    for (int mi = 0; mi < 2; mi++)
#pragma unroll
        for (int nt = 0; nt < 4; nt++)
#pragma unroll
            for (int q = 0; q < 4; q++) acc[mi][nt][q] = 0.0f;

    float4 st[4];

    auto load_Araw = [&](int kc) {
#pragma unroll
        for (int i = 0; i < 4; i++) {
            int seg = tid + i * 256;          // 0..1023: 128 rows x 8 segs(16B)
            int row = seg >> 3, s = seg & 7;
            int gm = m0 + row, gk = kc * 32 + s * 4;
            float4 v = make_float4(0.f, 0.f, 0.f, 0.f);
            if (gm < M && gk < EMB2) {
                v = *reinterpret_cast<const float4*>(Z1 + (size_t)gm * EMB2 + gk);
                float4 cs = *reinterpret_cast<const float4*>(g_sc1 + gk);
                float4 ds = *reinterpret_cast<const float4*>(g_sh1 + gk);
                v.x = fmaxf(fmaf(cs.x, v.x, ds.x), 0.f);
                v.y = fmaxf(fmaf(cs.y, v.y, ds.y), 0.f);
                v.z = fmaxf(fmaf(cs.z, v.z, ds.z), 0.f);
                v.w = fmaxf(fmaf(cs.w, v.w, ds.w), 0.f);
            }
            st[i] = v;
        }
    };
    auto store_A = [&](int buf) {
        uint32_t base = sb + buf * ASTAGE;
#pragma unroll
        for (int i = 0; i < 4; i++) {
            int seg = tid + i * 256;
            int row = seg >> 3, s = seg & 7;
            uint32_t off = swz64(row * 64 + s * 8);
            float4 v = st[i];
            __nv_bfloat162 H0 = __floats2bfloat162_rn(v.x, v.y);
            __nv_bfloat162 H1 = __floats2bfloat162_rn(v.z, v.w);
            __nv_bfloat162 L0 = __floats2bfloat162_rn(v.x - __low2float(H0), v.y - __high2float(H0));
            __nv_bfloat162 L1 = __floats2bfloat162_rn(v.z - __low2float(H1), v.w - __high2float(H1));
            sts64(base + off,        *reinterpret_cast<uint32_t*>(&H0),
                                     *reinterpret_cast<uint32_t*>(&H1));
            sts64(base + 8192 + off, *reinterpret_cast<uint32_t*>(&L0),
                                     *reinterpret_cast<uint32_t*>(&L1));
        }
    };
    auto load_B = [&](int kc, int buf) {
        uint32_t base = sb + BB + buf * BSTAGE;
        int row = tid >> 2, s = tid & 3;
        uint32_t so = swz64(row * 64 + s * 16);
        size_t rb = (size_t)(n0 + row) * KP2 + (size_t)kc * 32 + s * 8;
        cp_async16(base + so,        Bhi + rb);
        cp_async16(base + 4096 + so, Blo + rb);
        cp_commit();
    };

    load_Araw(0); store_A(0); load_B(0, 0);
    load_Araw(1);             load_B(1, 1);

    for (int j = 0; j < nch; j++) {
        if (j + 2 < nch) asm volatile("cp.async.wait_group 1;" ::: "memory");
        else             asm volatile("cp.async.wait_group 0;" ::: "memory");
        __syncthreads();

        uint32_t sA = sb + (j % 3) * ASTAGE;
        uint32_t sB = sb + BB + (j % 3) * BSTAGE;
#pragma unroll
        for (int ks = 0; ks < 2; ks++) {
            int seg = ks * 2 + khalf;
            uint32_t a[2][4], bh[2][4], bl[2][4];

#pragma unroll
            for (int mi = 0; mi < 2; mi++)
                ldsm_x4(a[mi], sA + swz64((arow_base + mi * 16) * 64 + seg * 16));
#pragma unroll
            for (int nj = 0; nj < 2; nj++)
                ldsm_x4(bh[nj], sB + swz64((brow_base + nj * 16) * 64 + seg * 16));

            // hh
#pragma unroll
            for (int mi = 0; mi < 2; mi++)
#pragma unroll
                for (int nt = 0; nt < 4; nt++)
                    mma16816(acc[mi][nt], a[mi], bh[nt >> 1][nt & 1], bh[nt >> 1][(nt & 1) + 2]);
            // hl
#pragma unroll
            for (int nj = 0; nj < 2; nj++)
                ldsm_x4(bl[nj], sB + 4096 + swz64((brow_base + nj * 16) * 64 + seg * 16));
#pragma unroll
            for (int mi = 0; mi < 2; mi++)
#pragma unroll
                for (int nt = 0; nt < 4; nt++)
                    mma16816(acc[mi][nt], a[mi], bl[nt >> 1][nt & 1], bl[nt >> 1][(nt & 1) + 2]);
            // lh
#pragma unroll
            for (int mi = 0; mi < 2; mi++)
                ldsm_x4(a[mi], sA + 8192 + swz64((arow_base + mi * 16) * 64 + seg * 16));
#pragma unroll
            for (int mi = 0; mi < 2; mi++)
#pragma unroll
                for (int nt = 0; nt < 4; nt++)
                    mma16816(acc[mi][nt], a[mi], bh[nt >> 1][nt & 1], bh[nt >> 1][(nt & 1) + 2]);
        }

        // stage chunk j+1's A (regs) into buf (j+1)%3 — not in use at iters j or j+1-read-barrier
        if (j + 1 < nch) store_A((j + 1) % 3);
        if (j + 2 < nch) { load_Araw(j + 2); load_B(j + 2, (j + 2) % 3); }
    }

    int rg = lane >> 2, cg = (lane & 3) * 2;
#pragma unroll
    for (int mi = 0; mi < 2; mi++) {
        int r0 = m0 + wm * 32 + mi * 16 + rg;
#pragma unroll
        for (int nt = 0; nt < 4; nt++) {
            int c0 = n0 + wn * 32 + nt * 8 + cg;
            if (c0 < NC) {
                if (r0 < M)
                    *reinterpret_cast<float2*>(C + (size_t)r0 * NC + c0) =
                        make_float2(acc[mi][nt][0], acc[mi][nt][1]);
                if (r0 + 8 < M)
                    *reinterpret_cast<float2*>(C + (size_t)(r0 + 8) * NC + c0) =
                        make_float2(acc[mi][nt][2], acc[mi][nt][3]);
            }
        }
    }

#pragma unroll
    for (int nt = 0; nt < 4; nt++) {
#pragma unroll
        for (int cp = 0; cp < 2; cp++) {
            float s = 0.f, q = 0.f;
#pragma unroll
            for (int mi = 0; mi < 2; mi++) {
                float v0 = acc[mi][nt][cp];
                float v1 = acc[mi][nt][cp + 2];
                s += v0 + v1;
                q += v0 * v0 + v1 * v1;
            }
#pragma unroll
            for (int off = 4; off <= 16; off <<= 1) {
                s += __shfl_xor_sync(0xFFFFFFFF, s, off);
                q += __shfl_xor_sync(0xFFFFFFFF, q, off);
            }
            if ((lane >> 2) == 0) {
                int c0 = n0 + wn * 32 + nt * 8 + (lane & 3) * 2 + cp;
                if (c0 < NC) {
                    atomicAdd(&g_sum[c0], (double)s);
                    atomicAdd(&g_sq[c0], (double)q);
                }
            }
        }
    }
}

// ---------------- launcher ----------------
extern "C" void kernel_launch(void* const* d_in, const int* in_sizes, int n_in,
                              void* d_out, int out_size) {
    const float* x    = (const float*)d_in[0];
    const float* Wb   = (const float*)d_in[1];
    const float* eps  = (const float*)d_in[2];
    const float* W1   = (const float*)d_in[3];
    const float* bn1g = (const float*)d_in[5];
    const float* bn1b = (const float*)d_in[6];
    const float* W2   = (const float*)d_in[7];
    const float* bng  = (const float*)d_in[9];
    const float* bnb  = (const float*)d_in[10];
    const int*   ei   = (const int*)d_in[11];
    const int*   ea   = (const int*)d_in[12];
    float* out = (float*)d_out;

    float *z1, *z2;
    __nv_bfloat16 *Ahi, *Alo, *Bhi, *Blo;
    cudaGetSymbolAddress((void**)&z1,  g_z1);
    cudaGetSymbolAddress((void**)&z2,  g_z2);
    cudaGetSymbolAddress((void**)&Ahi, g_Ahi);
    cudaGetSymbolAddress((void**)&Alo, g_Alo);
    cudaGetSymbolAddress((void**)&Bhi, g_Bhi);
    cudaGetSymbolAddress((void**)&Blo, g_Blo);

    const int SMEM1 = 3 * 24576;   // 72 KB, 3 CTAs/SM
    const int SMEM2 = 3 * 16384 + 3 * 8192;  // 72 KB, 2 CTAs/SM
    cudaFuncSetAttribute(gemm_s32,   cudaFuncAttributeMaxDynamicSharedMemorySize, SMEM1);
    cudaFuncSetAttribute(gemm_fused2, cudaFuncAttributeMaxDynamicSharedMemorySize, SMEM2);

    const int elems = Nn * EMB;
    const int mtiles = (Nn + 127) / 128;

    // ---- CSR build: once per launch ----
    csr_zero <<<(Nn + 255) / 256, 256>>>();
    csr_count<<<(Ee + 255) / 256, 256>>>(ei);
    csr_scan <<<1, 1024>>>();
    csr_fill <<<(Ee + 255) / 256, 256>>>(ei);

    for (int l = 0; l < LAYERS; l++) {
        prep1<<<NPAD1 + 10, 320>>>(W1 + (size_t)l * EMB2 * EMB, Wb + (size_t)l * EMB * 9);

        if (l == 0) gather_split<1><<<(Nn + 15) / 16, 512>>>(x,  ei, ea, eps, l);
        else        gather_split<0><<<(Nn + 15) / 16, 512>>>(z2, ei, ea, eps, l);

        gemm_s32<<<dim3(NPAD1 / 64, mtiles), 256, SMEM1>>>(
            Ahi, Alo, Bhi, Blo, z1, Nn, EMB2, KP1, NCHA);

        prep2<<<NPAD2 + 1, 320>>>(W2 + (size_t)l * EMB * EMB2,
                                  bn1g + (size_t)l * EMB2, bn1b + (size_t)l * EMB2);

        // GEMM2: BN1+relu+split fused into A-load; reads z1 fp32 directly
        gemm_fused2<<<dim3(NPAD2 / 64, mtiles), 256, SMEM2>>>(z1, Bhi, Blo, z2, Nn);

        bn_finalize2<<<1, 320>>>(bng + (size_t)l * EMB, bnb + (size_t)l * EMB);
    }

    bn_apply<<<(elems + 255) / 256, 256>>>(z2, out);
}

// round 17
// speedup vs baseline: 1.1349x; 1.1349x over previous
#include <cuda_runtime.h>
#include <cuda_bf16.h>
#include <cstdint>
#include <cstddef>

#define Nn   100000
#define Ee   256000
#define EMB  300
#define EMB2 600
#define LAYERS 5

#define KP1 320
#define KP2 640
#define NCHA 10     // KP1/32
#define NCHB 20     // KP2/32
#define NPAD1 640   // 10 n-tiles of 64
#define NPAD2 320   // 5 n-tiles of 64

// ---------------- device scratch ----------------
__device__ __align__(128) float  g_z1   [(size_t)Nn * EMB2];
__device__ __align__(128) float  g_z2   [(size_t)Nn * EMB];
__device__ __align__(128) __nv_bfloat16 g_Ahi[(size_t)Nn * KP2];
__device__ __align__(128) __nv_bfloat16 g_Alo[(size_t)Nn * KP2];
__device__ __align__(128) __nv_bfloat16 g_Bhi[262144];
__device__ __align__(128) __nv_bfloat16 g_Blo[262144];
__device__ __align__(16) float g_etab [9 * EMB];
__device__ double g_sum  [EMB2];
__device__ double g_sq   [EMB2];
__device__ __align__(16) float  g_sc1  [EMB2];
__device__ __align__(16) float  g_sh1  [EMB2];
__device__ __align__(16) float  g_sc2  [EMB];
__device__ __align__(16) float  g_sh2  [EMB];
// CSR (built once per launch)
__device__ int g_rowptr[Nn + 1];
__device__ int g_cnt   [Nn];
__device__ int g_elist [Ee];

// ---------------- PTX helpers ----------------
__device__ __forceinline__ uint32_t smem_u32(const void* p) {
    uint32_t a;
    asm("{ .reg .u64 t; cvta.to.shared.u64 t, %1; cvt.u32.u64 %0, t; }" : "=r"(a) : "l"(p));
    return a;
}
__device__ __forceinline__ void cp_async16(uint32_t dst, const void* src) {
    asm volatile("cp.async.cg.shared.global [%0], [%1], 16;" :: "r"(dst), "l"(src));
}
__device__ __forceinline__ void cp_async16p(uint32_t dst, const void* src, bool valid) {
    int sz = valid ? 16 : 0;
    asm volatile("cp.async.cg.shared.global [%0], [%1], 16, %2;" :: "r"(dst), "l"(src), "r"(sz));
}
__device__ __forceinline__ void cp_commit() { asm volatile("cp.async.commit_group;"); }
__device__ __forceinline__ uint32_t swz64(uint32_t b) { return b ^ ((b >> 3) & 0x30); }

__device__ __forceinline__ void ldsm_x4(uint32_t (&r)[4], uint32_t addr) {
    asm volatile("ldmatrix.sync.aligned.m8n8.x4.shared.b16 {%0,%1,%2,%3}, [%4];"
        : "=r"(r[0]), "=r"(r[1]), "=r"(r[2]), "=r"(r[3]) : "r"(addr));
}
__device__ __forceinline__ void mma16816(float (&d)[4], const uint32_t (&a)[4],
                                         uint32_t b0, uint32_t b1) {
    asm volatile("mma.sync.aligned.m16n8k16.row.col.f32.bf16.bf16.f32 "
        "{%0,%1,%2,%3}, {%4,%5,%6,%7}, {%8,%9}, {%0,%1,%2,%3};"
        : "+f"(d[0]), "+f"(d[1]), "+f"(d[2]), "+f"(d[3])
        : "r"(a[0]), "r"(a[1]), "r"(a[2]), "r"(a[3]), "r"(b0), "r"(b1));
}

// ---------------- CSR build (once per launch) ----------------
__global__ void csr_zero() {
    int i = blockIdx.x * blockDim.x + threadIdx.x;
    if (i < Nn) g_cnt[i] = 0;
}
__global__ void csr_count(const int* __restrict__ ei) {
    int e = blockIdx.x * blockDim.x + threadIdx.x;
    if (e < Ee) atomicAdd(&g_cnt[ei[Ee + e]], 1);
}
__global__ void __launch_bounds__(1024) csr_scan() {
    __shared__ int sums[1024];
    int t = threadIdx.x;
    const int CH = (Nn + 1023) / 1024;
    int start = t * CH;
    int end = min(start + CH, Nn);
    int s = 0;
    for (int i = start; i < end; i++) s += g_cnt[i];
    sums[t] = s;
    __syncthreads();
    for (int off = 1; off < 1024; off <<= 1) {
        int v = (t >= off) ? sums[t - off] : 0;
        __syncthreads();
        sums[t] += v;
        __syncthreads();
    }
    int run = (t == 0) ? 0 : sums[t - 1];
    for (int i = start; i < end; i++) { g_rowptr[i] = run; run += g_cnt[i]; }
    if (t == 1023) g_rowptr[Nn] = sums[1023];
    __syncthreads();
    for (int i = start; i < end; i++) g_cnt[i] = 0;
}
__global__ void csr_fill(const int* __restrict__ ei) {
    int e = blockIdx.x * blockDim.x + threadIdx.x;
    if (e < Ee) {
        int dst = ei[Ee + e];
        int pos = atomicAdd(&g_cnt[dst], 1);
        g_elist[g_rowptr[dst] + pos] = e;
    }
}

// ---------------- fused gather + BN-inline + bf16 split (feeds GEMM1) ----------------
template <int FIRST>
__global__ void __launch_bounds__(512)
gather_split(const float* __restrict__ Z, const int* __restrict__ ei,
             const int* __restrict__ ea, const float* __restrict__ eps, int l) {
    __shared__ __align__(16) float s_et[9 * EMB];
    for (int i = threadIdx.x; i < 9 * EMB; i += 512) s_et[i] = g_etab[i];
    __syncthreads();

    int warp = threadIdx.x >> 5, lane = threadIdx.x & 31;
    int n = blockIdx.x * 16 + warp;
    if (n >= Nn) return;

    float4 cs[3], ds[3];
    if (!FIRST) {
#pragma unroll
        for (int t = 0; t < 3; t++) {
            int k = lane + t * 32;
            if (k < 75) {
                cs[t] = *reinterpret_cast<const float4*>(g_sc2 + k * 4);
                ds[t] = *reinterpret_cast<const float4*>(g_sh2 + k * 4);
            }
        }
    }

    auto bn = [&](float4 z, int t) -> float4 {
        if (FIRST) return z;
        float4 o;
        o.x = fmaxf(fmaf(cs[t].x, z.x, ds[t].x), 0.f);
        o.y = fmaxf(fmaf(cs[t].y, z.y, ds[t].y), 0.f);
        o.z = fmaxf(fmaf(cs[t].z, z.z, ds[t].z), 0.f);
        o.w = fmaxf(fmaf(cs[t].w, z.w, ds[t].w), 0.f);
        return o;
    };

    float4 acc[3];
#pragma unroll
    for (int t = 0; t < 3; t++) acc[t] = make_float4(0.f, 0.f, 0.f, 0.f);

    int beg = __ldg(g_rowptr + n), stop = __ldg(g_rowptr + n + 1);
    for (int idx = beg; idx < stop; idx++) {
        int e   = __ldg(g_elist + idx);
        int src = __ldg(ei + e);
        int c   = __ldg(ea + 2 * e) * 3 + __ldg(ea + 2 * e + 1);
        const float4* zr = reinterpret_cast<const float4*>(Z + (size_t)src * EMB);
        const float4* er = reinterpret_cast<const float4*>(s_et + c * EMB);
#pragma unroll
        for (int t = 0; t < 3; t++) {
            int k = lane + t * 32;
            if (k < 75) {
                float4 hv = bn(__ldg(zr + k), t);
                float4 ev = er[k];
                acc[t].x += fmaxf(hv.x + ev.x, 0.f);
                acc[t].y += fmaxf(hv.y + ev.y, 0.f);
                acc[t].z += fmaxf(hv.z + ev.z, 0.f);
                acc[t].w += fmaxf(hv.w + ev.w, 0.f);
            }
        }
    }

    float f = 1.0f + __ldg(eps + l);
    const float4* zd = reinterpret_cast<const float4*>(Z + (size_t)n * EMB);
#pragma unroll
    for (int t = 0; t < 3; t++) {
        int k = lane + t * 32;
        if (k < 80) {
            float4 o = make_float4(0.f, 0.f, 0.f, 0.f);
            if (k < 75) {
                float4 hv = bn(__ldg(zd + k), t);
                o.x = fmaf(f, hv.x, acc[t].x);
                o.y = fmaf(f, hv.y, acc[t].y);
                o.z = fmaf(f, hv.z, acc[t].z);
                o.w = fmaf(f, hv.w, acc[t].w);
            }
            __nv_bfloat162 H0 = __floats2bfloat162_rn(o.x, o.y);
            __nv_bfloat162 H1 = __floats2bfloat162_rn(o.z, o.w);
            __nv_bfloat162 L0 = __floats2bfloat162_rn(o.x - __low2float(H0), o.y - __high2float(H0));
            __nv_bfloat162 L1 = __floats2bfloat162_rn(o.z - __low2float(H1), o.w - __high2float(H1));
            uint2 hv2 = make_uint2(*reinterpret_cast<uint32_t*>(&H0), *reinterpret_cast<uint32_t*>(&H1));
            uint2 lv2 = make_uint2(*reinterpret_cast<uint32_t*>(&L0), *reinterpret_cast<uint32_t*>(&L1));
            *reinterpret_cast<uint2*>(g_Ahi + (size_t)n * KP1 + k * 4) = hv2;
            *reinterpret_cast<uint2*>(g_Alo + (size_t)n * KP1 + k * 4) = lv2;
        }
    }
}

// ---------------- prep kernels ----------------
__global__ void prep1(const float* __restrict__ W1, const float* __restrict__ Wb) {
    int b = blockIdx.x, t = threadIdx.x;
    if (b < NPAD1) {
        float v = (b < EMB2 && t < EMB) ? W1[(size_t)b * EMB + t] : 0.0f;
        __nv_bfloat16 h = __float2bfloat16_rn(v);
        g_Bhi[(size_t)b * KP1 + t] = h;
        g_Blo[(size_t)b * KP1 + t] = __float2bfloat16_rn(v - __bfloat162float(h));
    } else if (b < NPAD1 + 9) {
        int c = b - NPAD1;
        if (t < EMB) g_etab[c * EMB + t] = Wb[t * 9 + c / 3] + Wb[t * 9 + 6 + (c % 3)];
    } else {
        for (int i = t; i < EMB2; i += blockDim.x) { g_sum[i] = 0.0; g_sq[i] = 0.0; }
    }
}

__global__ void prep2(const float* __restrict__ W2,
                      const float* __restrict__ gamma, const float* __restrict__ beta) {
    int b = blockIdx.x, t = threadIdx.x;
    if (b < NPAD2) {
        for (int c = t; c < KP2; c += blockDim.x) {
            float v = (b < EMB && c < EMB2) ? W2[(size_t)b * EMB2 + c] : 0.0f;
            __nv_bfloat16 h = __float2bfloat16_rn(v);
            g_Bhi[(size_t)b * KP2 + c] = h;
            g_Blo[(size_t)b * KP2 + c] = __float2bfloat16_rn(v - __bfloat162float(h));
        }
    } else {
        for (int i = t; i < EMB2; i += blockDim.x) {
            double m = g_sum[i] / (double)Nn;
            double v = g_sq[i] / (double)Nn - m * m;
            float rs = rsqrtf((float)v + 1e-5f);
            float a = gamma[i] * rs;
            g_sc1[i] = a;
            g_sh1[i] = beta[i] - a * (float)m;
        }
        __syncthreads();
        for (int i = t; i < EMB; i += blockDim.x) { g_sum[i] = 0.0; g_sq[i] = 0.0; }
    }
}

__global__ void bn_finalize2(const float* __restrict__ gamma, const float* __restrict__ beta) {
    int i = blockIdx.x * blockDim.x + threadIdx.x;
    if (i >= EMB) return;
    double m = g_sum[i] / (double)Nn;
    double v = g_sq[i] / (double)Nn - m * m;
    float rs = rsqrtf((float)v + 1e-5f);
    float a = gamma[i] * rs;
    g_sc2[i] = a;
    g_sh2[i] = beta[i] - a * (float)m;
}

__global__ void bn_apply(const float* __restrict__ Z, float* __restrict__ outh) {
    int i = blockIdx.x * blockDim.x + threadIdx.x;
    if (i >= Nn * EMB) return;
    int col = i % EMB;
    outh[i] = fmaf(g_sc2[col], Z[i], g_sh2[col]);
}

// ---------------- A split for GEMM2 (z1 -> BN1+relu -> hi/lo, KP2) ----------------
__global__ void __launch_bounds__(256)
split_A2(const float* __restrict__ src) {
    const int qpr = KP2 / 4;
    int i = blockIdx.x * blockDim.x + threadIdx.x;
    if (i >= Nn * qpr) return;
    int row = i / qpr;
    int col = (i - row * qpr) * 4;
    float4 v = make_float4(0.f, 0.f, 0.f, 0.f);
    if (col < EMB2) {
        v = *reinterpret_cast<const float4*>(src + (size_t)row * EMB2 + col);
        float4 cs = *reinterpret_cast<const float4*>(g_sc1 + col);
        float4 ds = *reinterpret_cast<const float4*>(g_sh1 + col);
        v.x = fmaxf(fmaf(cs.x, v.x, ds.x), 0.f);
        v.y = fmaxf(fmaf(cs.y, v.y, ds.y), 0.f);
        v.z = fmaxf(fmaf(cs.z, v.z, ds.z), 0.f);
        v.w = fmaxf(fmaf(cs.w, v.w, ds.w), 0.f);
    }
    __nv_bfloat162 H0 = __floats2bfloat162_rn(v.x, v.y);
    __nv_bfloat162 H1 = __floats2bfloat162_rn(v.z, v.w);
    __nv_bfloat162 L0 = __floats2bfloat162_rn(v.x - __low2float(H0), v.y - __high2float(H0));
    __nv_bfloat162 L1 = __floats2bfloat162_rn(v.z - __low2float(H1), v.w - __high2float(H1));
    uint2 hv = make_uint2(*reinterpret_cast<uint32_t*>(&H0), *reinterpret_cast<uint32_t*>(&H1));
    uint2 lv = make_uint2(*reinterpret_cast<uint32_t*>(&L0), *reinterpret_cast<uint32_t*>(&L1));
    *reinterpret_cast<uint2*>(g_Ahi + (size_t)row * KP2 + col) = hv;
    *reinterpret_cast<uint2*>(g_Alo + (size_t)row * KP2 + col) = lv;
}

// ---------------- split-bf16 GEMM: 128 threads, warp tile 64x32, CTA 128x64 ---------
// 4 warps (2M x 2N). Stage 24KB: Ah@0 Al@8K Bh@16K Bl@20K; 3 stages = 72KB; 3 CTAs/SM.
// Frag-reuse phases per k16 seg: hh -> hl -> lh. B frags reused across 4 mi-steps
// => 128 B of LDSM per MMA (was 170) — less smem crossbar pressure per unit work.
__global__ void __launch_bounds__(128, 3)
gemm_s32(const __nv_bfloat16* __restrict__ Ahi, const __nv_bfloat16* __restrict__ Alo,
         const __nv_bfloat16* __restrict__ Bhi, const __nv_bfloat16* __restrict__ Blo,
         float* __restrict__ C, int M, int NC, int KP, int nch) {
    extern __shared__ __align__(1024) char smem[];
    uint32_t sb = smem_u32(smem);
    const int STAGE = 24576;

    int tid = threadIdx.x;
    int wid = tid >> 5, lane = tid & 31;
    int wm = wid >> 1, wn = wid & 1;        // 2(M) x 2(N); warp tile 64x32
    int n0 = blockIdx.x * 64;
    int m0 = blockIdx.y * 128;

    int quad = lane >> 3, r = lane & 7;
    int arow_base = wm * 64 + (quad & 1) * 8 + r;   // + mi*16, mi=0..3
    int brow_base = wn * 32 + (quad & 1) * 8 + r;   // + nj*16, nj=0..1
    int khalf = quad >> 1;

    float acc[4][4][4];
#pragma unroll
    for (int mi = 0; mi < 4; mi++)
#pragma unroll
        for (int nt = 0; nt < 4; nt++)
#pragma unroll
            for (int q = 0; q < 4; q++) acc[mi][nt][q] = 0.0f;

    auto load_chunk = [&](int kc, int buf) {
        uint32_t s0 = sb + buf * STAGE;
        size_t aoff = (size_t)m0 * KP + (size_t)kc * 32;
        size_t boff = (size_t)n0 * KP + (size_t)kc * 32;
        // A: 128 rows x 64B = 512 segs; 128 threads -> 4 each (hi + lo)
#pragma unroll
        for (int i = 0; i < 4; i++) {
            int seg = tid + i * 128;
            int row = seg >> 2, s = seg & 3;
            uint32_t so = swz64(row * 64 + s * 16);
            size_t ra = aoff + (size_t)row * KP + s * 8;
            bool va = (m0 + row) < M;
            cp_async16p(s0 + so,        Ahi + ra, va);
            cp_async16p(s0 + 8192 + so, Alo + ra, va);
        }
        // B: 64 rows x 64B = 256 segs; 128 threads -> 2 each (hi + lo)
#pragma unroll
        for (int i = 0; i < 2; i++) {
            int seg = tid + i * 128;
            int row = seg >> 2, s = seg & 3;
            uint32_t so = swz64(row * 64 + s * 16);
            size_t rb = boff + (size_t)row * KP + s * 8;
            cp_async16(s0 + 16384 + so, Bhi + rb);
            cp_async16(s0 + 20480 + so, Blo + rb);
        }
        cp_commit();
    };

    load_chunk(0, 0);
    load_chunk(1, 1);

    for (int j = 0; j < nch; j++) {
        if (j + 2 < nch) asm volatile("cp.async.wait_group 1;" ::: "memory");
        else             asm volatile("cp.async.wait_group 0;" ::: "memory");
        __syncthreads();

        if (j + 2 < nch) load_chunk(j + 2, (j + 2) % 3);

        uint32_t s0 = sb + (j % 3) * STAGE;
#pragma unroll
        for (int ks = 0; ks < 2; ks++) {
            int seg = ks * 2 + khalf;
            uint32_t a[4][4], bh[2][4], bl[2][4];

            // load Ah (4 frags) + Bh (2 frags)
#pragma unroll
            for (int mi = 0; mi < 4; mi++)
                ldsm_x4(a[mi], s0 + swz64((arow_base + mi * 16) * 64 + seg * 16));
#pragma unroll
            for (int nj = 0; nj < 2; nj++)
                ldsm_x4(bh[nj], s0 + 16384 + swz64((brow_base + nj * 16) * 64 + seg * 16));

            // hh
#pragma unroll
            for (int mi = 0; mi < 4; mi++)
#pragma unroll
                for (int nt = 0; nt < 4; nt++)
                    mma16816(acc[mi][nt], a[mi], bh[nt >> 1][nt & 1], bh[nt >> 1][(nt & 1) + 2]);

            // hl
#pragma unroll
            for (int nj = 0; nj < 2; nj++)
                ldsm_x4(bl[nj], s0 + 20480 + swz64((brow_base + nj * 16) * 64 + seg * 16));
#pragma unroll
            for (int mi = 0; mi < 4; mi++)
#pragma unroll
                for (int nt = 0; nt < 4; nt++)
                    mma16816(acc[mi][nt], a[mi], bl[nt >> 1][nt & 1], bl[nt >> 1][(nt & 1) + 2]);

            // lh (reuse a[] for Al)
#pragma unroll
            for (int mi = 0; mi < 4; mi++)
                ldsm_x4(a[mi], s0 + 8192 + swz64((arow_base + mi * 16) * 64 + seg * 16));
#pragma unroll
            for (int mi = 0; mi < 4; mi++)
#pragma unroll
                for (int nt = 0; nt < 4; nt++)
                    mma16816(acc[mi][nt], a[mi], bh[nt >> 1][nt & 1], bh[nt >> 1][(nt & 1) + 2]);
        }
    }

    // ---- epilogue: C stores ----
    int rg = lane >> 2, cg = (lane & 3) * 2;
#pragma unroll
    for (int mi = 0; mi < 4; mi++) {
        int r0 = m0 + wm * 64 + mi * 16 + rg;
#pragma unroll
        for (int nt = 0; nt < 4; nt++) {
            int c0 = n0 + wn * 32 + nt * 8 + cg;
            if (c0 < NC) {
                if (r0 < M)
                    *reinterpret_cast<float2*>(C + (size_t)r0 * NC + c0) =
                        make_float2(acc[mi][nt][0], acc[mi][nt][1]);
                if (r0 + 8 < M)
                    *reinterpret_cast<float2*>(C + (size_t)(r0 + 8) * NC + c0) =
                        make_float2(acc[mi][nt][2], acc[mi][nt][3]);
            }
        }
    }

    // ---- epilogue: fused BN stats (padded rows zero => contribute 0) ----
#pragma unroll
    for (int nt = 0; nt < 4; nt++) {
#pragma unroll
        for (int cp = 0; cp < 2; cp++) {
            float s = 0.f, q = 0.f;
#pragma unroll
            for (int mi = 0; mi < 4; mi++) {
                float v0 = acc[mi][nt][cp];
                float v1 = acc[mi][nt][cp + 2];
                s += v0 + v1;
                q += v0 * v0 + v1 * v1;
            }
#pragma unroll
            for (int off = 4; off <= 16; off <<= 1) {
                s += __shfl_xor_sync(0xFFFFFFFF, s, off);
                q += __shfl_xor_sync(0xFFFFFFFF, q, off);
            }
            if ((lane >> 2) == 0) {
                int c0 = n0 + wn * 32 + nt * 8 + (lane & 3) * 2 + cp;
                if (c0 < NC) {
                    atomicAdd(&g_sum[c0], (double)s);
                    atomicAdd(&g_sq[c0], (double)q);
                }
            }
        }
    }
}

// ---------------- launcher ----------------
extern "C" void kernel_launch(void* const* d_in, const int* in_sizes, int n_in,
                              void* d_out, int out_size) {
    const float* x    = (const float*)d_in[0];
    const float* Wb   = (const float*)d_in[1];
    const float* eps  = (const float*)d_in[2];
    const float* W1   = (const float*)d_in[3];
    const float* bn1g = (const float*)d_in[5];
    const float* bn1b = (const float*)d_in[6];
    const float* W2   = (const float*)d_in[7];
    const float* bng  = (const float*)d_in[9];
    const float* bnb  = (const float*)d_in[10];
    const int*   ei   = (const int*)d_in[11];
    const int*   ea   = (const int*)d_in[12];
    float* out = (float*)d_out;

    float *z1, *z2;
    __nv_bfloat16 *Ahi, *Alo, *Bhi, *Blo;
    cudaGetSymbolAddress((void**)&z1,  g_z1);
    cudaGetSymbolAddress((void**)&z2,  g_z2);
    cudaGetSymbolAddress((void**)&Ahi, g_Ahi);
    cudaGetSymbolAddress((void**)&Alo, g_Alo);
    cudaGetSymbolAddress((void**)&Bhi, g_Bhi);
    cudaGetSymbolAddress((void**)&Blo, g_Blo);

    const int SMEM_BYTES = 3 * 24576;   // 72 KB -> 3 CTAs/SM
    cudaFuncSetAttribute(gemm_s32, cudaFuncAttributeMaxDynamicSharedMemorySize, SMEM_BYTES);

    const int elems = Nn * EMB;
    const int mtiles = (Nn + 127) / 128;

    // ---- CSR build: once per launch ----
    csr_zero <<<(Nn + 255) / 256, 256>>>();
    csr_count<<<(Ee + 255) / 256, 256>>>(ei);
    csr_scan <<<1, 1024>>>();
    csr_fill <<<(Ee + 255) / 256, 256>>>(ei);

    for (int l = 0; l < LAYERS; l++) {
        prep1<<<NPAD1 + 10, 320>>>(W1 + (size_t)l * EMB2 * EMB, Wb + (size_t)l * EMB * 9);

        if (l == 0) gather_split<1><<<(Nn + 15) / 16, 512>>>(x,  ei, ea, eps, l);
        else        gather_split<0><<<(Nn + 15) / 16, 512>>>(z2, ei, ea, eps, l);

        gemm_s32<<<dim3(NPAD1 / 64, mtiles), 128, SMEM_BYTES>>>(
            Ahi, Alo, Bhi, Blo, z1, Nn, EMB2, KP1, NCHA);

        prep2<<<NPAD2 + 1, 320>>>(W2 + (size_t)l * EMB * EMB2,
                                  bn1g + (size_t)l * EMB2, bn1b + (size_t)l * EMB2);

        split_A2<<<(Nn * (KP2 / 4) + 255) / 256, 256>>>(z1);

        gemm_s32<<<dim3(NPAD2 / 64, mtiles), 128, SMEM_BYTES>>>(
            Ahi, Alo, Bhi, Blo, z2, Nn, EMB, KP2, NCHB);

        bn_finalize2<<<1, 320>>>(bng + (size_t)l * EMB, bnb + (size_t)l * EMB);
    }

    bn_apply<<<(elems + 255) / 256, 256>>>(z2, out);
}